// round 1
// baseline (speedup 1.0000x reference)
#include <cuda_runtime.h>

#define BB 4096
#define TT 365
#define HH 64
#define G4 256
#define HORIZON 7
#define ROWS 32
#define NCTA (BB / ROWS)      // 128
#define NTHREADS 256
#define PW 260                // padded pitch (floats) for transposed weights

// ---- shared memory layout (float offsets) ----
#define OFF_W0  0
#define SZ_W0   (64 * PW)
#define OFF_W1  (OFF_W0 + SZ_W0)
#define SZ_W1   (128 * PW)
#define OFF_H0  (OFF_W1 + SZ_W1)
#define OFF_H1  (OFF_H0 + 64 * ROWS)
#define OFF_B0  (OFF_H1 + 64 * ROWS)
#define OFF_B1  (OFF_B0 + G4)
#define OFF_WI  (OFF_B1 + G4)
#define OFF_FCW (OFF_WI + G4)
#define OFF_PP  (OFF_FCW + HH)
#define OFF_PV  (OFF_PP + 8 * ROWS)
#define OFF_FCB (OFF_PV + ROWS)
#define SMEM_FLOATS (OFF_FCB + 4)
#define SMEM_BYTES  (SMEM_FLOATS * 4)

// ---- packed f32x2 helpers (Blackwell FFMA2 via PTX; ptxas won't auto-fuse) ----
__device__ __forceinline__ void fma2(unsigned long long &acc, unsigned long long a,
                                     unsigned long long b) {
    asm("fma.rn.f32x2 %0, %1, %2, %0;" : "+l"(acc) : "l"(a), "l"(b));
}
__device__ __forceinline__ unsigned long long pack2(float v) {
    unsigned long long r;
    asm("mov.b64 %0, {%1, %1};" : "=l"(r) : "r"(__float_as_uint(v)));
    return r;
}
__device__ __forceinline__ float2 unpack2(unsigned long long v) {
    unsigned int lo, hi;
    asm("mov.b64 {%0, %1}, %2;" : "=r"(lo), "=r"(hi) : "l"(v));
    return make_float2(__uint_as_float(lo), __uint_as_float(hi));
}

// ---- accurate-enough nonlinearities (MUFU ex2 + rcp, ~2 ulp) ----
__device__ __forceinline__ float sigm(float v) {
    return __fdividef(1.f, 1.f + __expf(-v));
}
__device__ __forceinline__ float tanh_(float v) {
    float a = fabsf(v);
    float e = __expf(-2.f * a);
    float r = __fdividef(1.f - e, 1.f + e);
    return copysignf(r, v);
}

// acc[g*4+p] holds gate columns (g*64 + jc*8 + 2p, +1) for this thread's row r.
__device__ __forceinline__ void initacc(unsigned long long acc[16], const float* bias, int jc) {
    #pragma unroll
    for (int g = 0; g < 4; ++g) {
        const ulonglong2* bp = reinterpret_cast<const ulonglong2*>(bias + g * 64 + jc * 8);
        ulonglong2 v0 = bp[0];
        ulonglong2 v1 = bp[1];
        acc[g * 4 + 0] = v0.x; acc[g * 4 + 1] = v0.y;
        acc[g * 4 + 2] = v1.x; acc[g * 4 + 3] = v1.y;
    }
}
__device__ __forceinline__ void addscaled(unsigned long long acc[16], const float* w, int jc,
                                          unsigned long long xx) {
    #pragma unroll
    for (int g = 0; g < 4; ++g) {
        const ulonglong2* wp = reinterpret_cast<const ulonglong2*>(w + g * 64 + jc * 8);
        ulonglong2 v0 = wp[0];
        ulonglong2 v1 = wp[1];
        fma2(acc[g * 4 + 0], v0.x, xx);
        fma2(acc[g * 4 + 1], v0.y, xx);
        fma2(acc[g * 4 + 2], v1.x, xx);
        fma2(acc[g * 4 + 3], v1.y, xx);
    }
}

// gates += h @ Wt   (Wt: [64][PW] k-major, all-lane-broadcast reads; h: [64][ROWS])
__device__ __forceinline__ void gemm64(unsigned long long acc[16], const float* __restrict__ wt,
                                       const float* __restrict__ hb, int r, int jc) {
    const float* wrow = wt + jc * 8;
    #pragma unroll 4
    for (int k = 0; k < 64; ++k) {
        unsigned long long hh = pack2(hb[k * ROWS + r]);
        const float* p = wrow + k * PW;
        #pragma unroll
        for (int g = 0; g < 4; ++g) {
            ulonglong2 wa = *reinterpret_cast<const ulonglong2*>(p + g * 64);
            ulonglong2 wb = *reinterpret_cast<const ulonglong2*>(p + g * 64 + 4);
            fma2(acc[g * 4 + 0], wa.x, hh);
            fma2(acc[g * 4 + 1], wa.y, hh);
            fma2(acc[g * 4 + 2], wb.x, hh);
            fma2(acc[g * 4 + 3], wb.y, hh);
        }
    }
}

__device__ __forceinline__ void cell(unsigned long long acc[16], float c[8], float hout[8]) {
    #pragma unroll
    for (int p = 0; p < 4; ++p) {
        float2 iv = unpack2(acc[p]);
        float2 fv = unpack2(acc[4 + p]);
        float2 gv = unpack2(acc[8 + p]);
        float2 ov = unpack2(acc[12 + p]);
        {
            float cn = sigm(fv.x) * c[2 * p] + sigm(iv.x) * tanh_(gv.x);
            c[2 * p] = cn;
            hout[2 * p] = sigm(ov.x) * tanh_(cn);
        }
        {
            float cn = sigm(fv.y) * c[2 * p + 1] + sigm(iv.y) * tanh_(gv.y);
            c[2 * p + 1] = cn;
            hout[2 * p + 1] = sigm(ov.y) * tanh_(cn);
        }
    }
}

// Transpose-load weights into SMEM:  W*T[k][col] = W[col][k]
__device__ void load_weights(float* sm, const float* __restrict__ whh0,
                             const float* __restrict__ wih1, const float* __restrict__ whh1,
                             const float* __restrict__ b0, const float* __restrict__ b1,
                             const float* __restrict__ wih0) {
    float* W0T = sm + OFF_W0;
    float* W1T = sm + OFF_W1;
    int tid = threadIdx.x;
    for (int e = tid; e < G4 * HH; e += NTHREADS) {
        int col = e >> 6;
        int k = e & 63;
        W0T[k * PW + col] = whh0[e];
        W1T[k * PW + col] = wih1[e];
        W1T[(k + 64) * PW + col] = whh1[e];
    }
    sm[OFF_B0 + tid] = b0[tid];
    sm[OFF_B1 + tid] = b1[tid];
    sm[OFF_WI + tid] = wih0[tid];
}

__global__ void __launch_bounds__(NTHREADS, 1)
lstm_kernel(const float* __restrict__ x,
            const float* __restrict__ eWih0, const float* __restrict__ eWhh0,
            const float* __restrict__ eb0,
            const float* __restrict__ eWih1, const float* __restrict__ eWhh1,
            const float* __restrict__ eb1,
            const float* __restrict__ dWih0, const float* __restrict__ dWhh0,
            const float* __restrict__ db0,
            const float* __restrict__ dWih1, const float* __restrict__ dWhh1,
            const float* __restrict__ db1,
            const float* __restrict__ fcW, const float* __restrict__ fcb,
            float* __restrict__ out) {
    extern __shared__ float sm[];
    const int tid = threadIdx.x;
    const int jc = tid >> 5;   // warp id: gate-chunk (8 hidden units, all 4 gates)
    const int r = tid & 31;    // lane: batch row within tile
    const int grow = blockIdx.x * ROWS + r;

    float* H0 = sm + OFF_H0;
    float* H1 = sm + OFF_H1;

    // ---------- encoder weights ----------
    load_weights(sm, eWhh0, eWih1, eWhh1, eb0, eb1, eWih0);
    for (int e = tid; e < 64 * ROWS; e += NTHREADS) { H0[e] = 0.f; H1[e] = 0.f; }
    __syncthreads();

    float c0[8], c1[8];
    #pragma unroll
    for (int u = 0; u < 8; ++u) { c0[u] = 0.f; c1[u] = 0.f; }

    const float* xrow = x + grow * TT;
    float xv = xrow[0];

    // ---------- encoder: 365 sequential steps ----------
    for (int t = 0; t < TT; ++t) {
        float xnext = (t + 1 < TT) ? xrow[t + 1] : 0.f;  // prefetch hides L2 latency

        unsigned long long acc[16];
        // layer 0: gates = b0 + x_t * Wih0 + h0 @ Whh0^T
        initacc(acc, sm + OFF_B0, jc);
        addscaled(acc, sm + OFF_WI, jc, pack2(xv));
        gemm64(acc, sm + OFF_W0, H0, r, jc);
        float h0r[8];
        cell(acc, c0, h0r);
        __syncthreads();                 // all layer-0 reads of H0 done
        #pragma unroll
        for (int u = 0; u < 8; ++u) H0[(jc * 8 + u) * ROWS + r] = h0r[u];
        __syncthreads();

        // layer 1: gates = b1 + h0 @ Wih1^T + h1 @ Whh1^T  (K=128 fused)
        initacc(acc, sm + OFF_B1, jc);
        gemm64(acc, sm + OFF_W1, H0, r, jc);
        gemm64(acc, sm + OFF_W1 + 64 * PW, H1, r, jc);
        float h1r[8];
        cell(acc, c1, h1r);
        __syncthreads();                 // all layer-1 reads of H1 done
        #pragma unroll
        for (int u = 0; u < 8; ++u) H1[(jc * 8 + u) * ROWS + r] = h1r[u];
        __syncthreads();

        xv = xnext;
    }

    // ---------- swap in decoder weights ----------
    load_weights(sm, dWhh0, dWih1, dWhh1, db0, db1, dWih0);
    if (tid < HH) sm[OFF_FCW + tid] = fcW[tid];
    if (tid == 0) sm[OFF_FCB] = fcb[0];
    __syncthreads();

    // ---------- decoder: 7 autoregressive steps ----------
    float din = 0.f;
    for (int s = 0; s < HORIZON; ++s) {
        unsigned long long acc[16];
        initacc(acc, sm + OFF_B0, jc);
        addscaled(acc, sm + OFF_WI, jc, pack2(din));
        gemm64(acc, sm + OFF_W0, H0, r, jc);
        float h0r[8];
        cell(acc, c0, h0r);
        __syncthreads();
        #pragma unroll
        for (int u = 0; u < 8; ++u) H0[(jc * 8 + u) * ROWS + r] = h0r[u];
        __syncthreads();

        initacc(acc, sm + OFF_B1, jc);
        gemm64(acc, sm + OFF_W1, H0, r, jc);
        gemm64(acc, sm + OFF_W1 + 64 * PW, H1, r, jc);
        float h1r[8];
        cell(acc, c1, h1r);

        // partial FC: this thread's 8 hidden units
        float part = 0.f;
        #pragma unroll
        for (int u = 0; u < 8; ++u) part += h1r[u] * sm[OFF_FCW + jc * 8 + u];

        __syncthreads();                 // layer-1 reads of old H1 done
        #pragma unroll
        for (int u = 0; u < 8; ++u) H1[(jc * 8 + u) * ROWS + r] = h1r[u];
        sm[OFF_PP + jc * ROWS + r] = part;
        __syncthreads();

        if (tid < ROWS) {
            float sum = sm[OFF_FCB];
            #pragma unroll
            for (int j = 0; j < 8; ++j) sum += sm[OFF_PP + j * ROWS + tid];
            out[(blockIdx.x * ROWS + tid) * HORIZON + s] = sum;
            sm[OFF_PV + tid] = sum;
        }
        __syncthreads();
        din = sm[OFF_PV + r];            // feedback becomes next decoder input
    }
}

extern "C" void kernel_launch(void* const* d_in, const int* in_sizes, int n_in,
                              void* d_out, int out_size) {
    cudaFuncSetAttribute(lstm_kernel, cudaFuncAttributeMaxDynamicSharedMemorySize, SMEM_BYTES);
    lstm_kernel<<<NCTA, NTHREADS, SMEM_BYTES>>>(
        (const float*)d_in[0],                                   // x
        (const float*)d_in[1], (const float*)d_in[2], (const float*)d_in[3],   // enc L0
        (const float*)d_in[4], (const float*)d_in[5], (const float*)d_in[6],   // enc L1
        (const float*)d_in[7], (const float*)d_in[8], (const float*)d_in[9],   // dec L0
        (const float*)d_in[10], (const float*)d_in[11], (const float*)d_in[12],// dec L1
        (const float*)d_in[13], (const float*)d_in[14],          // fc
        (float*)d_out);
}

// round 2
// speedup vs baseline: 1.2141x; 1.2141x over previous
#include <cuda_runtime.h>

#define BB 4096
#define TT 365
#define HH 64
#define G4 256
#define HORIZON 7
#define ROWS 32
#define NCTA (BB / ROWS)      // 128
#define NTHREADS 128
#define PW 256                // weight pitch (broadcast reads: no conflict, no pad needed)

// ---- shared memory layout (float offsets) ----
#define OFF_W0  0
#define OFF_W1  (OFF_W0 + 64 * PW)        // 16384
#define OFF_H0  (OFF_W1 + 128 * PW)       // 49152
#define OFF_H1  (OFF_H0 + 64 * ROWS)      // 51200
#define OFF_B0  (OFF_H1 + 64 * ROWS)      // 53248
#define OFF_B1  (OFF_B0 + G4)
#define OFF_WI  (OFF_B1 + G4)
#define OFF_FCW (OFF_WI + G4)
#define OFF_PP  (OFF_FCW + HH)
#define OFF_PV  (OFF_PP + 8 * ROWS)
#define OFF_FCB (OFF_PV + ROWS)
#define SMEM_FLOATS (OFF_FCB + 4)
#define SMEM_BYTES  (SMEM_FLOATS * 4)      // ~217.5 KB

typedef unsigned long long ull;

// ---- packed f32x2 (Blackwell FFMA2 via PTX; ptxas won't auto-fuse) ----
__device__ __forceinline__ void fma2(ull &acc, ull a, ull b) {
    asm("fma.rn.f32x2 %0, %1, %2, %0;" : "+l"(acc) : "l"(a), "l"(b));
}
__device__ __forceinline__ ull pack2(float v) {
    ull r;
    asm("mov.b64 %0, {%1, %1};" : "=l"(r) : "r"(__float_as_uint(v)));
    return r;
}
__device__ __forceinline__ float2 unpack2(ull v) {
    unsigned int lo, hi;
    asm("mov.b64 {%0, %1}, %2;" : "=r"(lo), "=r"(hi) : "l"(v));
    return make_float2(__uint_as_float(lo), __uint_as_float(hi));
}

// ---- nonlinearities (MUFU ex2 + rcp, ~2 ulp) ----
__device__ __forceinline__ float sigm(float v) {
    return __fdividef(1.f, 1.f + __expf(-v));
}
__device__ __forceinline__ float tanh_(float v) {
    float a = fabsf(v);
    float e = __expf(-2.f * a);
    float r = __fdividef(1.f - e, 1.f + e);
    return copysignf(r, v);
}

// acc[g*4+p] holds gate cols (g*64 + jc*8 + 2p, +1) for one batch row.
__device__ __forceinline__ void initacc(ull acc[16], const float* bias, int jc) {
    #pragma unroll
    for (int g = 0; g < 4; ++g) {
        const ulonglong2* bp = reinterpret_cast<const ulonglong2*>(bias + g * 64 + jc * 8);
        ulonglong2 v0 = bp[0];
        ulonglong2 v1 = bp[1];
        acc[g * 4 + 0] = v0.x; acc[g * 4 + 1] = v0.y;
        acc[g * 4 + 2] = v1.x; acc[g * 4 + 3] = v1.y;
    }
}

// acc{A,B} += x{A,B} * w   (rank-1 input term, weights broadcast from SMEM)
__device__ __forceinline__ void addscaled2(ull accA[16], ull accB[16], const float* w, int jc,
                                           ull xA, ull xB) {
    #pragma unroll
    for (int g = 0; g < 4; ++g) {
        const ulonglong2* wp = reinterpret_cast<const ulonglong2*>(w + g * 64 + jc * 8);
        ulonglong2 v0 = wp[0];
        ulonglong2 v1 = wp[1];
        fma2(accA[g * 4 + 0], v0.x, xA); fma2(accB[g * 4 + 0], v0.x, xB);
        fma2(accA[g * 4 + 1], v0.y, xA); fma2(accB[g * 4 + 1], v0.y, xB);
        fma2(accA[g * 4 + 2], v1.x, xA); fma2(accB[g * 4 + 2], v1.x, xB);
        fma2(accA[g * 4 + 3], v1.y, xA); fma2(accB[g * 4 + 3], v1.y, xB);
    }
}

// gates{A,B} += h{A,B} @ Wt. Wt: [64][PW] k-major (broadcast reads);
// h: [64 units][32 rows]; this thread owns rows 2rp, 2rp+1 (one LDS.64 per k).
__device__ __forceinline__ void gemm64x2(ull accA[16], ull accB[16],
                                         const float* __restrict__ wt,
                                         const float* __restrict__ hb, int rp, int jc) {
    const float* wrow = wt + jc * 8;
    const float2* h2 = reinterpret_cast<const float2*>(hb) + rp;  // stride 16 float2 per k
    #pragma unroll 4
    for (int k = 0; k < 64; ++k) {
        float2 hv = h2[k * 16];
        ull hA = pack2(hv.x);
        ull hB = pack2(hv.y);
        const float* p = wrow + k * PW;
        #pragma unroll
        for (int g = 0; g < 4; ++g) {
            ulonglong2 wa = *reinterpret_cast<const ulonglong2*>(p + g * 64);
            ulonglong2 wb = *reinterpret_cast<const ulonglong2*>(p + g * 64 + 4);
            fma2(accA[g * 4 + 0], wa.x, hA); fma2(accB[g * 4 + 0], wa.x, hB);
            fma2(accA[g * 4 + 1], wa.y, hA); fma2(accB[g * 4 + 1], wa.y, hB);
            fma2(accA[g * 4 + 2], wb.x, hA); fma2(accB[g * 4 + 2], wb.x, hB);
            fma2(accA[g * 4 + 3], wb.y, hA); fma2(accB[g * 4 + 3], wb.y, hB);
        }
    }
}

__device__ __forceinline__ void cell(ull acc[16], float c[8], float hout[8]) {
    #pragma unroll
    for (int p = 0; p < 4; ++p) {
        float2 iv = unpack2(acc[p]);
        float2 fv = unpack2(acc[4 + p]);
        float2 gv = unpack2(acc[8 + p]);
        float2 ov = unpack2(acc[12 + p]);
        {
            float cn = sigm(fv.x) * c[2 * p] + sigm(iv.x) * tanh_(gv.x);
            c[2 * p] = cn;
            hout[2 * p] = sigm(ov.x) * tanh_(cn);
        }
        {
            float cn = sigm(fv.y) * c[2 * p + 1] + sigm(iv.y) * tanh_(gv.y);
            c[2 * p + 1] = cn;
            hout[2 * p + 1] = sigm(ov.y) * tanh_(cn);
        }
    }
}

// Store h pairs: H[(jc*8+u)*32 + 2rp .. +1] = {hA[u], hB[u]}
__device__ __forceinline__ void storeh(float* H, int jc, int rp, const float hA[8],
                                       const float hB[8]) {
    #pragma unroll
    for (int u = 0; u < 8; ++u)
        *reinterpret_cast<float2*>(H + (jc * 8 + u) * ROWS + 2 * rp) = make_float2(hA[u], hB[u]);
}

// Transpose-load weights into SMEM:  W*T[k][col] = W[col][k]
__device__ void load_weights(float* sm, const float* __restrict__ whh0,
                             const float* __restrict__ wih1, const float* __restrict__ whh1,
                             const float* __restrict__ b0, const float* __restrict__ b1,
                             const float* __restrict__ wih0) {
    float* W0T = sm + OFF_W0;
    float* W1T = sm + OFF_W1;
    int tid = threadIdx.x;
    for (int e = tid; e < G4 * HH; e += NTHREADS) {
        int col = e >> 6;
        int k = e & 63;
        W0T[k * PW + col] = whh0[e];
        W1T[k * PW + col] = wih1[e];
        W1T[(k + 64) * PW + col] = whh1[e];
    }
    sm[OFF_B0 + tid] = b0[tid];
    sm[OFF_B0 + tid + NTHREADS] = b0[tid + NTHREADS];
    sm[OFF_B1 + tid] = b1[tid];
    sm[OFF_B1 + tid + NTHREADS] = b1[tid + NTHREADS];
    sm[OFF_WI + tid] = wih0[tid];
    sm[OFF_WI + tid + NTHREADS] = wih0[tid + NTHREADS];
}

__global__ void __launch_bounds__(NTHREADS, 1)
lstm_kernel(const float* __restrict__ x,
            const float* __restrict__ eWih0, const float* __restrict__ eWhh0,
            const float* __restrict__ eb0,
            const float* __restrict__ eWih1, const float* __restrict__ eWhh1,
            const float* __restrict__ eb1,
            const float* __restrict__ dWih0, const float* __restrict__ dWhh0,
            const float* __restrict__ db0,
            const float* __restrict__ dWih1, const float* __restrict__ dWhh1,
            const float* __restrict__ db1,
            const float* __restrict__ fcW, const float* __restrict__ fcb,
            float* __restrict__ out) {
    extern __shared__ float sm[];
    const int tid = threadIdx.x;
    const int jc = tid >> 4;        // 0..7: gate-chunk (8 hidden units × 4 gates = 32 cols)
    const int rp = tid & 15;        // row-pair index: rows 2rp, 2rp+1
    const int rowA = blockIdx.x * ROWS + 2 * rp;

    float* H0 = sm + OFF_H0;
    float* H1 = sm + OFF_H1;

    // ---------- encoder weights ----------
    load_weights(sm, eWhh0, eWih1, eWhh1, eb0, eb1, eWih0);
    for (int e = tid; e < 64 * ROWS; e += NTHREADS) { H0[e] = 0.f; H1[e] = 0.f; }
    __syncthreads();

    float c0A[8], c0B[8], c1A[8], c1B[8];
    #pragma unroll
    for (int u = 0; u < 8; ++u) { c0A[u] = 0.f; c0B[u] = 0.f; c1A[u] = 0.f; c1B[u] = 0.f; }

    const float* xrowA = x + rowA * TT;
    const float* xrowB = xrowA + TT;
    float xvA = xrowA[0];
    float xvB = xrowB[0];

    // ---------- encoder: 365 sequential steps ----------
    for (int t = 0; t < TT; ++t) {
        float xnA = (t + 1 < TT) ? xrowA[t + 1] : 0.f;   // prefetch hides L2 latency
        float xnB = (t + 1 < TT) ? xrowB[t + 1] : 0.f;

        ull accA[16], accB[16];
        // layer 0: gates = b0 + x_t * Wih0 + h0 @ Whh0^T
        initacc(accA, sm + OFF_B0, jc);
        initacc(accB, sm + OFF_B0, jc);
        addscaled2(accA, accB, sm + OFF_WI, jc, pack2(xvA), pack2(xvB));
        gemm64x2(accA, accB, sm + OFF_W0, H0, rp, jc);
        float h0A[8], h0B[8];
        cell(accA, c0A, h0A);
        cell(accB, c0B, h0B);
        __syncthreads();                 // all layer-0 reads of H0 done
        storeh(H0, jc, rp, h0A, h0B);
        __syncthreads();

        // layer 1: gates = b1 + h0 @ Wih1^T + h1 @ Whh1^T  (K=128 fused)
        initacc(accA, sm + OFF_B1, jc);
        initacc(accB, sm + OFF_B1, jc);
        gemm64x2(accA, accB, sm + OFF_W1, H0, rp, jc);
        gemm64x2(accA, accB, sm + OFF_W1 + 64 * PW, H1, rp, jc);
        float h1A[8], h1B[8];
        cell(accA, c1A, h1A);
        cell(accB, c1B, h1B);
        __syncthreads();                 // all layer-1 reads of H1 done
        storeh(H1, jc, rp, h1A, h1B);
        __syncthreads();

        xvA = xnA;
        xvB = xnB;
    }

    // ---------- swap in decoder weights ----------
    load_weights(sm, dWhh0, dWih1, dWhh1, db0, db1, dWih0);
    if (tid < HH) sm[OFF_FCW + tid] = fcW[tid];
    if (tid == 0) sm[OFF_FCB] = fcb[0];
    __syncthreads();

    // ---------- decoder: 7 autoregressive steps ----------
    float dinA = 0.f, dinB = 0.f;
    for (int s = 0; s < HORIZON; ++s) {
        ull accA[16], accB[16];
        initacc(accA, sm + OFF_B0, jc);
        initacc(accB, sm + OFF_B0, jc);
        addscaled2(accA, accB, sm + OFF_WI, jc, pack2(dinA), pack2(dinB));
        gemm64x2(accA, accB, sm + OFF_W0, H0, rp, jc);
        float h0A[8], h0B[8];
        cell(accA, c0A, h0A);
        cell(accB, c0B, h0B);
        __syncthreads();
        storeh(H0, jc, rp, h0A, h0B);
        __syncthreads();

        initacc(accA, sm + OFF_B1, jc);
        initacc(accB, sm + OFF_B1, jc);
        gemm64x2(accA, accB, sm + OFF_W1, H0, rp, jc);
        gemm64x2(accA, accB, sm + OFF_W1 + 64 * PW, H1, rp, jc);
        float h1A[8], h1B[8];
        cell(accA, c1A, h1A);
        cell(accB, c1B, h1B);

        // partial FC over this thread's 8 hidden units, per row
        float partA = 0.f, partB = 0.f;
        #pragma unroll
        for (int u = 0; u < 8; ++u) {
            float w = sm[OFF_FCW + jc * 8 + u];
            partA += h1A[u] * w;
            partB += h1B[u] * w;
        }

        __syncthreads();                 // layer-1 reads of old H1 done
        storeh(H1, jc, rp, h1A, h1B);
        *reinterpret_cast<float2*>(sm + OFF_PP + jc * ROWS + 2 * rp) = make_float2(partA, partB);
        __syncthreads();

        if (tid < ROWS) {
            float sum = sm[OFF_FCB];
            #pragma unroll
            for (int j = 0; j < 8; ++j) sum += sm[OFF_PP + j * ROWS + tid];
            out[(blockIdx.x * ROWS + tid) * HORIZON + s] = sum;
            sm[OFF_PV + tid] = sum;
        }
        __syncthreads();
        float2 dv = *reinterpret_cast<const float2*>(sm + OFF_PV + 2 * rp);
        dinA = dv.x;                      // feedback becomes next decoder input
        dinB = dv.y;
    }
}

extern "C" void kernel_launch(void* const* d_in, const int* in_sizes, int n_in,
                              void* d_out, int out_size) {
    cudaFuncSetAttribute(lstm_kernel, cudaFuncAttributeMaxDynamicSharedMemorySize, SMEM_BYTES);
    lstm_kernel<<<NCTA, NTHREADS, SMEM_BYTES>>>(
        (const float*)d_in[0],                                   // x
        (const float*)d_in[1], (const float*)d_in[2], (const float*)d_in[3],   // enc L0
        (const float*)d_in[4], (const float*)d_in[5], (const float*)d_in[6],   // enc L1
        (const float*)d_in[7], (const float*)d_in[8], (const float*)d_in[9],   // dec L0
        (const float*)d_in[10], (const float*)d_in[11], (const float*)d_in[12],// dec L1
        (const float*)d_in[13], (const float*)d_in[14],          // fc
        (float*)d_out);
}

// round 3
// speedup vs baseline: 1.3663x; 1.1254x over previous
#include <cuda_runtime.h>

#define BB 4096
#define TT 365
#define HH 64
#define G4 256
#define HORIZON 7
#define ROWS 32
#define NCTA (BB / ROWS)      // 128
#define NTHREADS 256
#define PW 256

// ---- shared memory layout (float offsets) ----
#define OFF_W0   0
#define OFF_W1   (OFF_W0 + 64 * PW)         // 16384
#define OFF_H0A  (OFF_W1 + 128 * PW)        // 49152  (ping)
#define OFF_H0B  (OFF_H0A + 64 * ROWS)      // 51200  (pong)
#define OFF_H1   (OFF_H0B + 64 * ROWS)      // 53248
#define OFF_B0   (OFF_H1 + 64 * ROWS)       // 55296
#define OFF_B1   (OFF_B0 + G4)
#define OFF_WI   (OFF_B1 + G4)
#define OFF_FCW  (OFF_WI + G4)
#define OFF_PP   (OFF_FCW + HH)             // 32 uc-groups x 32 rows
#define OFF_PV   (OFF_PP + 32 * ROWS)
#define OFF_FCB  (OFF_PV + ROWS)
#define SMEM_FLOATS (OFF_FCB + 4)
#define SMEM_BYTES  (SMEM_FLOATS * 4)       // ~228.8 KB

typedef unsigned long long ull;

// ---- packed f32x2 (Blackwell FFMA2 via PTX; ptxas won't auto-fuse) ----
__device__ __forceinline__ void fma2(ull &acc, ull a, ull b) {
    asm("fma.rn.f32x2 %0, %1, %2, %0;" : "+l"(acc) : "l"(a), "l"(b));
}
__device__ __forceinline__ ull pack2(float v) {
    ull r;
    asm("mov.b64 %0, {%1, %1};" : "=l"(r) : "r"(__float_as_uint(v)));
    return r;
}
__device__ __forceinline__ float2 unpack2(ull v) {
    unsigned int lo, hi;
    asm("mov.b64 {%0, %1}, %2;" : "=r"(lo), "=r"(hi) : "l"(v));
    return make_float2(__uint_as_float(lo), __uint_as_float(hi));
}

// ---- nonlinearities (MUFU ex2 + rcp, ~2 ulp) ----
__device__ __forceinline__ float sigm(float v) {
    return __fdividef(1.f, 1.f + __expf(-v));
}
__device__ __forceinline__ float tanh_(float v) {
    float a = fabsf(v);
    float e = __expf(-2.f * a);
    float r = __fdividef(1.f - e, 1.f + e);
    return copysignf(r, v);
}

// Thread tile: 4 batch rows (rq) x 8 gate-cols (uc -> 2 hidden units x 4 gates).
// acc[j][g]: ull = gate-col pair (g*64 + uc*2, +1) for batch row 4rq+j.

__device__ __forceinline__ void initacc(ull acc[4][4], const float* bias, int uc) {
    ull b[4];
    #pragma unroll
    for (int g = 0; g < 4; ++g)
        b[g] = *reinterpret_cast<const ull*>(bias + g * 64 + uc * 2);
    #pragma unroll
    for (int j = 0; j < 4; ++j)
        #pragma unroll
        for (int g = 0; g < 4; ++g)
            acc[j][g] = b[g];
}

// acc[j] += x[j] * Wih0-cols (rank-1 input term)
__device__ __forceinline__ void addx(ull acc[4][4], const float* w, int uc, const float xv[4]) {
    ull wg[4];
    #pragma unroll
    for (int g = 0; g < 4; ++g)
        wg[g] = *reinterpret_cast<const ull*>(w + g * 64 + uc * 2);
    #pragma unroll
    for (int j = 0; j < 4; ++j) {
        ull xx = pack2(xv[j]);
        #pragma unroll
        for (int g = 0; g < 4; ++g) fma2(acc[j][g], wg[g], xx);
    }
}

// gates += h @ Wt.  Wt: [64][PW] k-major (broadcast LDS.64 per gate);
// h: [64 units][32 rows], this thread owns rows 4rq..4rq+3 (one LDS.128 per k).
__device__ __forceinline__ void gemm64(ull acc[4][4], const float* __restrict__ wt,
                                       const float* __restrict__ hb, int rq, int uc) {
    const float* wbase = wt + uc * 2;
    const float4* h4 = reinterpret_cast<const float4*>(hb) + rq;   // stride 8 float4 per k
    #pragma unroll 8
    for (int k = 0; k < 64; ++k) {
        float4 hv = h4[k * 8];
        const float* p = wbase + k * PW;
        ull w0 = *reinterpret_cast<const ull*>(p);
        ull w1 = *reinterpret_cast<const ull*>(p + 64);
        ull w2 = *reinterpret_cast<const ull*>(p + 128);
        ull w3 = *reinterpret_cast<const ull*>(p + 192);
        ull h0 = pack2(hv.x), h1 = pack2(hv.y), h2 = pack2(hv.z), h3 = pack2(hv.w);
        fma2(acc[0][0], w0, h0); fma2(acc[1][0], w0, h1);
        fma2(acc[2][0], w0, h2); fma2(acc[3][0], w0, h3);
        fma2(acc[0][1], w1, h0); fma2(acc[1][1], w1, h1);
        fma2(acc[2][1], w1, h2); fma2(acc[3][1], w1, h3);
        fma2(acc[0][2], w2, h0); fma2(acc[1][2], w2, h1);
        fma2(acc[2][2], w2, h2); fma2(acc[3][2], w2, h3);
        fma2(acc[0][3], w3, h0); fma2(acc[1][3], w3, h1);
        fma2(acc[2][3], w3, h2); fma2(acc[3][3], w3, h3);
    }
}

// c/h: [row j][unit e] with units 2uc+e
__device__ __forceinline__ void cell(ull acc[4][4], float c[4][2], float h[4][2]) {
    #pragma unroll
    for (int j = 0; j < 4; ++j) {
        float2 iv = unpack2(acc[j][0]);
        float2 fv = unpack2(acc[j][1]);
        float2 gv = unpack2(acc[j][2]);
        float2 ov = unpack2(acc[j][3]);
        {
            float cn = sigm(fv.x) * c[j][0] + sigm(iv.x) * tanh_(gv.x);
            c[j][0] = cn;
            h[j][0] = sigm(ov.x) * tanh_(cn);
        }
        {
            float cn = sigm(fv.y) * c[j][1] + sigm(iv.y) * tanh_(gv.y);
            c[j][1] = cn;
            h[j][1] = sigm(ov.y) * tanh_(cn);
        }
    }
}

// H[(2uc+e)*32 + 4rq + j] = h[j][e]  -> two STS.128, conflict-free
__device__ __forceinline__ void storeh(float* H, int uc, int rq, const float h[4][2]) {
    *reinterpret_cast<float4*>(H + (2 * uc + 0) * ROWS + 4 * rq) =
        make_float4(h[0][0], h[1][0], h[2][0], h[3][0]);
    *reinterpret_cast<float4*>(H + (2 * uc + 1) * ROWS + 4 * rq) =
        make_float4(h[0][1], h[1][1], h[2][1], h[3][1]);
}

// Transpose-load weights into SMEM:  W*T[k][col] = W[col][k]
__device__ void load_weights(float* sm, const float* __restrict__ whh0,
                             const float* __restrict__ wih1, const float* __restrict__ whh1,
                             const float* __restrict__ b0, const float* __restrict__ b1,
                             const float* __restrict__ wih0) {
    float* W0T = sm + OFF_W0;
    float* W1T = sm + OFF_W1;
    int tid = threadIdx.x;
    for (int e = tid; e < G4 * HH; e += NTHREADS) {
        int col = e >> 6;
        int k = e & 63;
        W0T[k * PW + col] = whh0[e];
        W1T[k * PW + col] = wih1[e];
        W1T[(k + 64) * PW + col] = whh1[e];
    }
    sm[OFF_B0 + tid] = b0[tid];
    sm[OFF_B1 + tid] = b1[tid];
    sm[OFF_WI + tid] = wih0[tid];
}

__global__ void __launch_bounds__(NTHREADS, 1)
lstm_kernel(const float* __restrict__ x,
            const float* __restrict__ eWih0, const float* __restrict__ eWhh0,
            const float* __restrict__ eb0,
            const float* __restrict__ eWih1, const float* __restrict__ eWhh1,
            const float* __restrict__ eb1,
            const float* __restrict__ dWih0, const float* __restrict__ dWhh0,
            const float* __restrict__ db0,
            const float* __restrict__ dWih1, const float* __restrict__ dWhh1,
            const float* __restrict__ db1,
            const float* __restrict__ fcW, const float* __restrict__ fcb,
            float* __restrict__ out) {
    extern __shared__ float sm[];
    const int tid = threadIdx.x;
    const int rq = tid & 7;         // row-quad: batch rows 4rq..4rq+3
    const int uc = tid >> 3;        // 0..31: col-group (2 hidden units x 4 gates)
    const int row0 = blockIdx.x * ROWS + 4 * rq;

    float* H0buf[2] = { sm + OFF_H0A, sm + OFF_H0B };
    float* H1 = sm + OFF_H1;

    // ---------- encoder weights ----------
    load_weights(sm, eWhh0, eWih1, eWhh1, eb0, eb1, eWih0);
    for (int e = tid; e < 3 * 64 * ROWS; e += NTHREADS) sm[OFF_H0A + e] = 0.f;
    __syncthreads();

    float c0[4][2], c1[4][2];
    #pragma unroll
    for (int j = 0; j < 4; ++j) { c0[j][0] = c0[j][1] = 0.f; c1[j][0] = c1[j][1] = 0.f; }

    const float* xr = x + row0 * TT;
    float xv[4];
    #pragma unroll
    for (int j = 0; j < 4; ++j) xv[j] = xr[j * TT];

    // ---------- encoder: 365 sequential steps ----------
    for (int t = 0; t < TT; ++t) {
        float xn[4];
        #pragma unroll
        for (int j = 0; j < 4; ++j)
            xn[j] = (t + 1 < TT) ? xr[j * TT + t + 1] : 0.f;   // prefetch hides L2

        float* H0r = H0buf[t & 1];
        float* H0w = H0buf[(t + 1) & 1];

        ull acc[4][4];
        // layer 0: gates = b0 + x_t * Wih0 + h0 @ Whh0^T   (reads ping, writes pong)
        initacc(acc, sm + OFF_B0, uc);
        addx(acc, sm + OFF_WI, uc, xv);
        gemm64(acc, sm + OFF_W0, H0r, rq, uc);
        float h0[4][2];
        cell(acc, c0, h0);
        storeh(H0w, uc, rq, h0);
        __syncthreads();                       // h0 visible; (no WAR: ping-pong)

        // layer 1: gates = b1 + h0 @ Wih1^T + h1 @ Whh1^T
        initacc(acc, sm + OFF_B1, uc);
        gemm64(acc, sm + OFF_W1, H0w, rq, uc);
        gemm64(acc, sm + OFF_W1 + 64 * PW, H1, rq, uc);
        float h1[4][2];
        cell(acc, c1, h1);
        __syncthreads();                       // all reads of H1 done before overwrite
        storeh(H1, uc, rq, h1);

        #pragma unroll
        for (int j = 0; j < 4; ++j) xv[j] = xn[j];
    }
    __syncthreads();                           // final H1 stores visible; weight readers done

    // ---------- swap in decoder weights ----------
    load_weights(sm, dWhh0, dWih1, dWhh1, db0, db1, dWih0);
    if (tid < HH) sm[OFF_FCW + tid] = fcW[tid];
    if (tid == 0) sm[OFF_FCB] = fcb[0];
    __syncthreads();

    // ---------- decoder: 7 autoregressive steps ----------
    float din[4] = {0.f, 0.f, 0.f, 0.f};
    for (int s = 0; s < HORIZON; ++s) {
        int t = TT + s;
        float* H0r = H0buf[t & 1];
        float* H0w = H0buf[(t + 1) & 1];

        ull acc[4][4];
        initacc(acc, sm + OFF_B0, uc);
        addx(acc, sm + OFF_WI, uc, din);
        gemm64(acc, sm + OFF_W0, H0r, rq, uc);
        float h0[4][2];
        cell(acc, c0, h0);
        storeh(H0w, uc, rq, h0);
        __syncthreads();

        initacc(acc, sm + OFF_B1, uc);
        gemm64(acc, sm + OFF_W1, H0w, rq, uc);
        gemm64(acc, sm + OFF_W1 + 64 * PW, H1, rq, uc);
        float h1[4][2];
        cell(acc, c1, h1);

        // partial FC over this thread's 2 hidden units, per row
        float w0 = sm[OFF_FCW + 2 * uc], w1 = sm[OFF_FCW + 2 * uc + 1];
        float part[4];
        #pragma unroll
        for (int j = 0; j < 4; ++j) part[j] = h1[j][0] * w0 + h1[j][1] * w1;

        __syncthreads();                       // reads of old H1 done
        storeh(H1, uc, rq, h1);
        *reinterpret_cast<float4*>(sm + OFF_PP + uc * ROWS + 4 * rq) =
            make_float4(part[0], part[1], part[2], part[3]);
        __syncthreads();

        if (tid < ROWS) {
            float sum = sm[OFF_FCB];
            #pragma unroll
            for (int g = 0; g < 32; ++g) sum += sm[OFF_PP + g * ROWS + tid];
            out[(blockIdx.x * ROWS + tid) * HORIZON + s] = sum;
            sm[OFF_PV + tid] = sum;
        }
        __syncthreads();
        float4 dv = *reinterpret_cast<const float4*>(sm + OFF_PV + 4 * rq);
        din[0] = dv.x; din[1] = dv.y; din[2] = dv.z; din[3] = dv.w;
    }
}

extern "C" void kernel_launch(void* const* d_in, const int* in_sizes, int n_in,
                              void* d_out, int out_size) {
    cudaFuncSetAttribute(lstm_kernel, cudaFuncAttributeMaxDynamicSharedMemorySize, SMEM_BYTES);
    lstm_kernel<<<NCTA, NTHREADS, SMEM_BYTES>>>(
        (const float*)d_in[0],                                   // x
        (const float*)d_in[1], (const float*)d_in[2], (const float*)d_in[3],   // enc L0
        (const float*)d_in[4], (const float*)d_in[5], (const float*)d_in[6],   // enc L1
        (const float*)d_in[7], (const float*)d_in[8], (const float*)d_in[9],   // dec L0
        (const float*)d_in[10], (const float*)d_in[11], (const float*)d_in[12],// dec L1
        (const float*)d_in[13], (const float*)d_in[14],          // fc
        (float*)d_out);
}